// round 2
// baseline (speedup 1.0000x reference)
#include <cuda_runtime.h>
#include <math.h>

// Problem constants
#define B_ 8
#define M_ 2048
#define IN_ 512
#define H_ 8
#define D_ 64
#define HD_ 512   // H_*D_

// Scratch (allocation-free rule: __device__ globals)
__device__ float g_Q[(size_t)B_ * M_ * HD_];
__device__ float g_K[(size_t)B_ * M_ * HD_];
__device__ float g_V[(size_t)B_ * M_ * HD_];
__device__ float g_C[(size_t)B_ * M_ * HD_];

// ---------------------------------------------------------------------------
// Tiled fp32 GEMM: C[M,N] = A[M,K] @ W[K,N] (+ bias). 64x64 tile, BK=16,
// 256 threads, 4x4 register blocking.
// ---------------------------------------------------------------------------
template <bool HAS_BIAS>
__global__ void __launch_bounds__(256) gemm64(
    const float* __restrict__ A, const float* __restrict__ W,
    const float* __restrict__ bias, float* __restrict__ C,
    int Mdim, int Ndim, int Kdim)
{
    __shared__ float As[16][65];  // [k][m], padded -> conflict-free transp. store
    __shared__ float Bs[16][64];  // [k][n]

    const int tid = threadIdx.x;
    const int tx = tid & 15, ty = tid >> 4;
    const int m0 = blockIdx.y * 64, n0 = blockIdx.x * 64;

    const int arow = tid >> 2, acol = (tid & 3) * 4;   // A tile: 64 rows x 16 cols
    const int brow = tid >> 4, bcol = (tid & 15) * 4;  // B tile: 16 rows x 64 cols

    float acc[4][4] = {};

    for (int k0 = 0; k0 < Kdim; k0 += 16) {
        float4 av = *(const float4*)(A + (size_t)(m0 + arow) * Kdim + k0 + acol);
        float4 bv = *(const float4*)(W + (size_t)(k0 + brow) * Ndim + n0 + bcol);
        As[acol + 0][arow] = av.x;
        As[acol + 1][arow] = av.y;
        As[acol + 2][arow] = av.z;
        As[acol + 3][arow] = av.w;
        *(float4*)&Bs[brow][bcol] = bv;
        __syncthreads();

#pragma unroll
        for (int kk = 0; kk < 16; kk++) {
            float a0 = As[kk][ty * 4 + 0];
            float a1 = As[kk][ty * 4 + 1];
            float a2 = As[kk][ty * 4 + 2];
            float a3 = As[kk][ty * 4 + 3];
            float4 b = *(const float4*)&Bs[kk][tx * 4];
            acc[0][0] += a0 * b.x; acc[0][1] += a0 * b.y; acc[0][2] += a0 * b.z; acc[0][3] += a0 * b.w;
            acc[1][0] += a1 * b.x; acc[1][1] += a1 * b.y; acc[1][2] += a1 * b.z; acc[1][3] += a1 * b.w;
            acc[2][0] += a2 * b.x; acc[2][1] += a2 * b.y; acc[2][2] += a2 * b.z; acc[2][3] += a2 * b.w;
            acc[3][0] += a3 * b.x; acc[3][1] += a3 * b.y; acc[3][2] += a3 * b.z; acc[3][3] += a3 * b.w;
        }
        __syncthreads();
    }

#pragma unroll
    for (int i = 0; i < 4; i++) {
        int m = m0 + ty * 4 + i;
        int n = n0 + tx * 4;
        float4 r;
        r.x = acc[i][0]; r.y = acc[i][1]; r.z = acc[i][2]; r.w = acc[i][3];
        if (HAS_BIAS) {
            r.x += bias[n + 0]; r.y += bias[n + 1];
            r.z += bias[n + 2]; r.w += bias[n + 3];
        }
        *(float4*)&C[(size_t)m * Ndim + n] = r;
    }
}

// ---------------------------------------------------------------------------
// Flash attention, fp32 CUDA cores.
// CTA = (b, h, 64-query tile). 8 warps x 8 query rows. 64-key tiles.
// Lane owns keys {lane, lane+32} for S, dims {lane, lane+32} for O.
// logits multiplied by sqrt(512) per the reference (divide by HEAD_DIM**-0.5).
// ---------------------------------------------------------------------------
__global__ void __launch_bounds__(256) attn64(
    const float* __restrict__ Q, const float* __restrict__ K,
    const float* __restrict__ V, float* __restrict__ O)
{
    extern __shared__ float sm[];
    float (*Qs)[65] = (float(*)[65])(sm);
    float (*Ks)[65] = (float(*)[65])(sm + 64 * 65);
    float (*Vs)[65] = (float(*)[65])(sm + 2 * 64 * 65);
    float (*Ps)[65] = (float(*)[65])(sm + 3 * 64 * 65);

    const int tid  = threadIdx.x;
    const int lane = tid & 31, warp = tid >> 5;
    const int bh   = blockIdx.y;
    const int b    = bh >> 3, h = bh & 7;
    const int q0   = blockIdx.x * 64;
    const size_t base = (size_t)b * M_ * HD_ + (size_t)h * D_;  // + m*HD_ + d

    // Load Q tile (64 rows x 64 dims)
#pragma unroll
    for (int p = 0; p < 4; p++) {
        int row = p * 16 + (tid >> 4);
        int c4  = (tid & 15) * 4;
        float4 v = *(const float4*)(Q + base + (size_t)(q0 + row) * HD_ + c4);
        Qs[row][c4 + 0] = v.x; Qs[row][c4 + 1] = v.y;
        Qs[row][c4 + 2] = v.z; Qs[row][c4 + 3] = v.w;
    }

    float o0[8] = {}, o1[8] = {};
    float mrow[8], lrow[8];
#pragma unroll
    for (int r = 0; r < 8; r++) { mrow[r] = -INFINITY; lrow[r] = 0.0f; }

    const int r0 = warp * 8;
    const float scale = 22.62741699796952f;  // sqrt(512)

    for (int kt = 0; kt < M_ / 64; kt++) {
        __syncthreads();
        // Load K,V tiles
#pragma unroll
        for (int p = 0; p < 4; p++) {
            int row = p * 16 + (tid >> 4);
            int c4  = (tid & 15) * 4;
            const size_t g = base + (size_t)(kt * 64 + row) * HD_ + c4;
            float4 kv = *(const float4*)(K + g);
            float4 vv = *(const float4*)(V + g);
            Ks[row][c4 + 0] = kv.x; Ks[row][c4 + 1] = kv.y;
            Ks[row][c4 + 2] = kv.z; Ks[row][c4 + 3] = kv.w;
            Vs[row][c4 + 0] = vv.x; Vs[row][c4 + 1] = vv.y;
            Vs[row][c4 + 2] = vv.z; Vs[row][c4 + 3] = vv.w;
        }
        __syncthreads();

        // S = Q K^T  (per-warp rows r0..r0+7, lane keys lane & lane+32)
        float s0[8] = {}, s1[8] = {};
#pragma unroll 4
        for (int d = 0; d < 64; d++) {
            float k0v = Ks[lane][d];
            float k1v = Ks[lane + 32][d];
#pragma unroll
            for (int r = 0; r < 8; r++) {
                float qv = Qs[r0 + r][d];
                s0[r] += qv * k0v;
                s1[r] += qv * k1v;
            }
        }

        // Online softmax per row
#pragma unroll
        for (int r = 0; r < 8; r++) {
            float v0 = s0[r] * scale, v1 = s1[r] * scale;
            float tmax = fmaxf(v0, v1);
#pragma unroll
            for (int off = 16; off > 0; off >>= 1)
                tmax = fmaxf(tmax, __shfl_xor_sync(0xffffffffu, tmax, off));
            float mnew = fmaxf(mrow[r], tmax);
            float p0 = __expf(v0 - mnew);
            float p1 = __expf(v1 - mnew);
            float psum = p0 + p1;
#pragma unroll
            for (int off = 16; off > 0; off >>= 1)
                psum += __shfl_xor_sync(0xffffffffu, psum, off);
            float corr = __expf(mrow[r] - mnew);
            lrow[r] = lrow[r] * corr + psum;
            o0[r] *= corr;
            o1[r] *= corr;
            mrow[r] = mnew;
            Ps[r0 + r][lane]      = p0;
            Ps[r0 + r][lane + 32] = p1;
        }
        __syncwarp();

        // O += P V (lane owns dims lane & lane+32)
#pragma unroll 4
        for (int k = 0; k < 64; k++) {
            float v0 = Vs[k][lane];
            float v1 = Vs[k][lane + 32];
#pragma unroll
            for (int r = 0; r < 8; r++) {
                float pv = Ps[r0 + r][k];
                o0[r] += pv * v0;
                o1[r] += pv * v1;
            }
        }
    }

    // Normalize + write merged context [B, M, H*D]
#pragma unroll
    for (int r = 0; r < 8; r++) {
        float inv = 1.0f / lrow[r];
        size_t idx = base + (size_t)(q0 + r0 + r) * HD_;
        O[idx + lane]      = o0[r] * inv;
        O[idx + lane + 32] = o1[r] * inv;
    }
}

// ---------------------------------------------------------------------------
extern "C" void kernel_launch(void* const* d_in, const int* in_sizes, int n_in,
                              void* d_out, int out_size)
{
    const float* x  = (const float*)d_in[0];
    const float* Wq = (const float*)d_in[1];
    const float* Wk = (const float*)d_in[2];
    const float* Wv = (const float*)d_in[3];
    const float* Wo = (const float*)d_in[4];
    const float* bo = (const float*)d_in[5];
    float* out = (float*)d_out;

    float *Qp, *Kp, *Vp, *Cp;
    cudaGetSymbolAddress((void**)&Qp, g_Q);
    cudaGetSymbolAddress((void**)&Kp, g_K);
    cudaGetSymbolAddress((void**)&Vp, g_V);
    cudaGetSymbolAddress((void**)&Cp, g_C);

    const int BM = B_ * M_;  // 16384 rows

    // QKV projections
    dim3 gQKV(HD_ / 64, BM / 64);
    gemm64<false><<<gQKV, 256>>>(x, Wq, nullptr, Qp, BM, HD_, IN_);
    gemm64<false><<<gQKV, 256>>>(x, Wk, nullptr, Kp, BM, HD_, IN_);
    gemm64<false><<<gQKV, 256>>>(x, Wv, nullptr, Vp, BM, HD_, IN_);

    // Attention
    size_t smem = (size_t)4 * 64 * 65 * sizeof(float);  // 66560 B
    cudaFuncSetAttribute(attn64, cudaFuncAttributeMaxDynamicSharedMemorySize,
                         (int)smem);
    attn64<<<dim3(M_ / 64, B_ * H_), 256, smem>>>(Qp, Kp, Vp, Cp);

    // Output projection + bias
    gemm64<true><<<dim3(IN_ / 64, BM / 64), 256>>>(Cp, Wo, bo, out, BM, IN_, HD_);
}

// round 4
// speedup vs baseline: 2.7920x; 2.7920x over previous
#include <cuda_runtime.h>
#include <cuda_bf16.h>
#include <stdint.h>
#include <math.h>

#define B_ 8
#define M_ 2048
#define HD_ 512
#define BM_ (B_*M_)
#define SCALE_ 22.62741699796952f   // reference divides by HEAD_DIM**-0.5

typedef __nv_bfloat16 bf16;
typedef __nv_bfloat162 bf162;

// ---------------- device scratch (allocation-free rule) ----------------
__device__ __align__(16) bf16 g_Xh[(size_t)BM_*HD_], g_Xl[(size_t)BM_*HD_];
__device__ __align__(16) bf16 g_Qh[(size_t)BM_*HD_], g_Ql[(size_t)BM_*HD_];
__device__ __align__(16) bf16 g_Kh[(size_t)BM_*HD_], g_Kl[(size_t)BM_*HD_];
__device__ __align__(16) bf16 g_Vh[(size_t)BM_*HD_], g_Vl[(size_t)BM_*HD_];
__device__ __align__(16) bf16 g_Ch[(size_t)BM_*HD_], g_Cl[(size_t)BM_*HD_];
__device__ __align__(16) bf16 g_Wh[4][512*512], g_Wl[4][512*512];   // W^T: [n][k]

// ---------------- helpers ----------------
__device__ __forceinline__ uint32_t smem_u32(const void* p) {
    uint32_t a;
    asm("{ .reg .u64 t; cvta.to.shared.u64 t, %1; cvt.u32.u64 %0, t; }" : "=r"(a) : "l"(p));
    return a;
}
#define SWZ(x) ((uint32_t)(x) ^ ((((uint32_t)(x)) >> 3) & 0x70))

__device__ __forceinline__ void ldm4(uint32_t (&r)[4], uint32_t a) {
    asm volatile("ldmatrix.sync.aligned.m8n8.x4.shared.b16 {%0,%1,%2,%3}, [%4];"
                 : "=r"(r[0]), "=r"(r[1]), "=r"(r[2]), "=r"(r[3]) : "r"(a));
}
__device__ __forceinline__ void ldm4t(uint32_t (&r)[4], uint32_t a) {
    asm volatile("ldmatrix.sync.aligned.m8n8.x4.trans.shared.b16 {%0,%1,%2,%3}, [%4];"
                 : "=r"(r[0]), "=r"(r[1]), "=r"(r[2]), "=r"(r[3]) : "r"(a));
}
__device__ __forceinline__ void mma_bf(float (&d)[4], const uint32_t (&a)[4],
                                       uint32_t b0, uint32_t b1) {
    asm volatile("mma.sync.aligned.m16n8k16.row.col.f32.bf16.bf16.f32 "
                 "{%0,%1,%2,%3}, {%4,%5,%6,%7}, {%8,%9}, {%0,%1,%2,%3};"
                 : "+f"(d[0]), "+f"(d[1]), "+f"(d[2]), "+f"(d[3])
                 : "r"(a[0]), "r"(a[1]), "r"(a[2]), "r"(a[3]), "r"(b0), "r"(b1));
}
__device__ __forceinline__ void splitf(float x, bf16& h, bf16& l) {
    h = __float2bfloat16(x);
    l = __float2bfloat16(x - __bfloat162float(h));
}

// ---------------- prep kernels ----------------
__global__ void __launch_bounds__(512) prep_x(const float4* __restrict__ x,
                                              bf16* __restrict__ xh, bf16* __restrict__ xl) {
    size_t i = (size_t)blockIdx.x * 512 + threadIdx.x;
    float4 v = x[i];
    bf16 h0, l0, h1, l1, h2, l2, h3, l3;
    splitf(v.x, h0, l0); splitf(v.y, h1, l1);
    splitf(v.z, h2, l2); splitf(v.w, h3, l3);
    bf162 a, b, c, d;
    a.x = h0; a.y = h1; b.x = h2; b.y = h3;
    c.x = l0; c.y = l1; d.x = l2; d.y = l3;
    *(bf162*)(xh + i * 4) = a; *(bf162*)(xh + i * 4 + 2) = b;
    *(bf162*)(xl + i * 4) = c; *(bf162*)(xl + i * 4 + 2) = d;
}

__global__ void __launch_bounds__(512) prep_w(const float* __restrict__ W,
                                              bf16* __restrict__ th, bf16* __restrict__ tl) {
    int n = blockIdx.x, k = threadIdx.x;
    float v = W[k * 512 + n];
    bf16 h, l; splitf(v, h, l);
    th[n * 512 + k] = h;
    tl[n * 512 + k] = l;
}

// ===========================================================================
// GEMM via mma.sync: C[16384,512] = A(hi/lo [m,512]) @ W^T(hi/lo [n,512])
// CTA 128x128, 8 warps (2x4), warp tile 64x32, split-bf16 3-pass.
// MODE 0: write bf16 hi/lo in [b,h,m,d].   MODE 2: fp32 + bias.
// ===========================================================================
#define G_AH 0
#define G_AL 16384
#define G_BH 32768
#define G_BL 49152
#define G_SZ 65536

template <int MODE>
__global__ void __launch_bounds__(256) gemm_mma(
    const bf16* __restrict__ Ah_, const bf16* __restrict__ Al_,
    const bf16* __restrict__ Bh_, const bf16* __restrict__ Bl_,
    const float* __restrict__ bias, float* __restrict__ out32,
    bf16* __restrict__ oh, bf16* __restrict__ ol)
{
    extern __shared__ char sm[];
    const uint32_t sb = smem_u32(sm);
    const int tid = threadIdx.x, warp = tid >> 5, lane = tid & 31;
    const int wm = warp >> 2, wn = warp & 3;
    const int lr = lane & 7, g = lane >> 3;
    const int offAr = (g & 1) * 8 + lr, offAc = (g >> 1) * 8;
    const int offBr = (g >> 1) * 8 + lr, offBc = (g & 1) * 8;
    const int m0 = blockIdx.y * 128, n0 = blockIdx.x * 128;

    float acc[4][4][4];
#pragma unroll
    for (int a = 0; a < 4; a++)
#pragma unroll
        for (int b = 0; b < 4; b++)
#pragma unroll
            for (int c = 0; c < 4; c++) acc[a][b][c] = 0.0f;

    for (int ch = 0; ch < 8; ch++) {
        if (ch) __syncthreads();
#pragma unroll
        for (int i = 0; i < 4; i++) {
            int t = i * 256 + tid, row = t >> 3, cb = (t & 7) * 16;
            uint32_t dsw = SWZ(row * 128 + cb);
            size_t abyte = ((size_t)(m0 + row) * 512 + ch * 64) * 2 + cb;
            size_t bbyte = ((size_t)(n0 + row) * 512 + ch * 64) * 2 + cb;
            *(uint4*)(sm + G_AH + dsw) = *(const uint4*)((const char*)Ah_ + abyte);
            *(uint4*)(sm + G_AL + dsw) = *(const uint4*)((const char*)Al_ + abyte);
            *(uint4*)(sm + G_BH + dsw) = *(const uint4*)((const char*)Bh_ + bbyte);
            *(uint4*)(sm + G_BL + dsw) = *(const uint4*)((const char*)Bl_ + bbyte);
        }
        __syncthreads();
#pragma unroll
        for (int ks = 0; ks < 4; ks++) {
            uint32_t bhF[2][4], blF[2][4];
#pragma unroll
            for (int np = 0; np < 2; np++) {
                uint32_t boff = SWZ((wn * 32 + np * 16 + offBr) * 128 + (ks * 16 + offBc) * 2);
                ldm4(bhF[np], sb + G_BH + boff);
                ldm4(blF[np], sb + G_BL + boff);
            }
#pragma unroll
            for (int mf = 0; mf < 4; mf++) {
                uint32_t aoff = SWZ((wm * 64 + mf * 16 + offAr) * 128 + (ks * 16 + offAc) * 2);
                uint32_t ah2[4], al2[4];
                ldm4(ah2, sb + G_AH + aoff);
                ldm4(al2, sb + G_AL + aoff);
#pragma unroll
                for (int nf = 0; nf < 4; nf++) {
                    int np = nf >> 1, hh = nf & 1;
                    uint32_t b0h = bhF[np][hh * 2], b1h = bhF[np][hh * 2 + 1];
                    uint32_t b0l = blF[np][hh * 2], b1l = blF[np][hh * 2 + 1];
                    mma_bf(acc[mf][nf], ah2, b0h, b1h);
                    mma_bf(acc[mf][nf], ah2, b0l, b1l);
                    mma_bf(acc[mf][nf], al2, b0h, b1h);
                }
            }
        }
    }

    // epilogue (accums already in regs)
#pragma unroll
    for (int mf = 0; mf < 4; mf++) {
        int rlo = m0 + wm * 64 + mf * 16 + (lane >> 2);
        int rhi = rlo + 8;
#pragma unroll
        for (int nf = 0; nf < 4; nf++) {
            int n = n0 + wn * 32 + nf * 8 + (lane & 3) * 2;
            if (MODE == 2) {
                float2 v0, v1;
                v0.x = acc[mf][nf][0] + bias[n]; v0.y = acc[mf][nf][1] + bias[n + 1];
                v1.x = acc[mf][nf][2] + bias[n]; v1.y = acc[mf][nf][3] + bias[n + 1];
                *(float2*)(out32 + (size_t)rlo * 512 + n) = v0;
                *(float2*)(out32 + (size_t)rhi * 512 + n) = v1;
            } else {
                int h = n >> 6, d = n & 63;
                {
                    int b = rlo >> 11, mm = rlo & 2047;
                    size_t base = ((size_t)(b * 8 + h) * 2048 + mm) * 64 + d;
                    bf16 h0, l0, h1, l1;
                    splitf(acc[mf][nf][0], h0, l0); splitf(acc[mf][nf][1], h1, l1);
                    bf162 t, u; t.x = h0; t.y = h1; u.x = l0; u.y = l1;
                    *(bf162*)(oh + base) = t; *(bf162*)(ol + base) = u;
                }
                {
                    int b = rhi >> 11, mm = rhi & 2047;
                    size_t base = ((size_t)(b * 8 + h) * 2048 + mm) * 64 + d;
                    bf16 h0, l0, h1, l1;
                    splitf(acc[mf][nf][2], h0, l0); splitf(acc[mf][nf][3], h1, l1);
                    bf162 t, u; t.x = h0; t.y = h1; u.x = l0; u.y = l1;
                    *(bf162*)(oh + base) = t; *(bf162*)(ol + base) = u;
                }
            }
        }
    }
}

// ===========================================================================
// Flash attention via mma.sync. CTA = (128-q tile, b*h). 256 threads, 8 warps.
// ===========================================================================
#define A_QH  0
#define A_QL  16384
#define A_KH  32768
#define A_KL  49152
#define A_VH  65536
#define A_VL  81920
#define A_PH0 98304
#define A_PH1 114688
#define A_PL0 131072
#define A_PL1 147456
#define A_WMX 163840
#define A_WSM 165888
#define A_MRN 167936
#define A_LRN 168448
#define A_CRR 168960
#define A_SZ  169472

__global__ void __launch_bounds__(256) attn_mma(
    const bf16* __restrict__ Qh, const bf16* __restrict__ Ql,
    const bf16* __restrict__ Kh, const bf16* __restrict__ Kl,
    const bf16* __restrict__ Vh, const bf16* __restrict__ Vl,
    bf16* __restrict__ Ch, bf16* __restrict__ Cl)
{
    extern __shared__ char sm[];
    const uint32_t sb = smem_u32(sm);
    float* wmax = (float*)(sm + A_WMX);   // [4][128]
    float* wsum = (float*)(sm + A_WSM);   // [4][128]
    float* mrun = (float*)(sm + A_MRN);   // [128]
    float* lrun = (float*)(sm + A_LRN);   // [128]
    float* crr  = (float*)(sm + A_CRR);   // [128]

    const int tid = threadIdx.x, warp = tid >> 5, lane = tid & 31;
    const int wm = warp >> 2, wn = warp & 3;
    const int lr = lane & 7, g = lane >> 3;
    const int offAr = (g & 1) * 8 + lr, offAc = (g >> 1) * 8;
    const int offBr = (g >> 1) * 8 + lr, offBc = (g & 1) * 8;
    const int bh = blockIdx.y, q0 = blockIdx.x * 128;

    if (tid < 128) { mrun[tid] = -INFINITY; lrun[tid] = 0.0f; }

    // Q tiles (hi/lo), 128x64, contiguous 128B rows
    {
        const char* qhp = (const char*)Qh + ((size_t)bh * 2048 + q0) * 128;
        const char* qlp = (const char*)Ql + ((size_t)bh * 2048 + q0) * 128;
#pragma unroll
        for (int i = 0; i < 4; i++) {
            int t = i * 256 + tid, row = t >> 3, cb = (t & 7) * 16;
            uint32_t dsw = SWZ(row * 128 + cb);
            *(uint4*)(sm + A_QH + dsw) = *(const uint4*)(qhp + row * 128 + cb);
            *(uint4*)(sm + A_QL + dsw) = *(const uint4*)(qlp + row * 128 + cb);
        }
    }

    float oacc[4][2][4];
#pragma unroll
    for (int a = 0; a < 4; a++)
#pragma unroll
        for (int b = 0; b < 2; b++)
#pragma unroll
            for (int c = 0; c < 4; c++) oacc[a][b][c] = 0.0f;

    for (int kt = 0; kt < 16; kt++) {
        __syncthreads();   // prev-iter readers done (and Q/init visible at kt=0)
        {
            const char* khp = (const char*)Kh + ((size_t)bh * 2048 + kt * 128) * 128;
            const char* klp = (const char*)Kl + ((size_t)bh * 2048 + kt * 128) * 128;
            const char* vhp = (const char*)Vh + ((size_t)bh * 2048 + kt * 128) * 128;
            const char* vlp = (const char*)Vl + ((size_t)bh * 2048 + kt * 128) * 128;
#pragma unroll
            for (int i = 0; i < 4; i++) {
                int t = i * 256 + tid, row = t >> 3, cb = (t & 7) * 16;
                uint32_t dsw = SWZ(row * 128 + cb);
                *(uint4*)(sm + A_KH + dsw) = *(const uint4*)(khp + row * 128 + cb);
                *(uint4*)(sm + A_KL + dsw) = *(const uint4*)(klp + row * 128 + cb);
                *(uint4*)(sm + A_VH + dsw) = *(const uint4*)(vhp + row * 128 + cb);
                *(uint4*)(sm + A_VL + dsw) = *(const uint4*)(vlp + row * 128 + cb);
            }
        }
        __syncthreads();

        // ---- S = Q K^T (warp tile 64x32) ----
        float sacc[4][4][4];
#pragma unroll
        for (int a = 0; a < 4; a++)
#pragma unroll
            for (int b = 0; b < 4; b++)
#pragma unroll
                for (int c = 0; c < 4; c++) sacc[a][b][c] = 0.0f;

#pragma unroll
        for (int ks = 0; ks < 4; ks++) {
            uint32_t kh2[2][4], kl2[2][4];
#pragma unroll
            for (int np = 0; np < 2; np++) {
                uint32_t boff = SWZ((wn * 32 + np * 16 + offBr) * 128 + (ks * 16 + offBc) * 2);
                ldm4(kh2[np], sb + A_KH + boff);
                ldm4(kl2[np], sb + A_KL + boff);
            }
#pragma unroll
            for (int mf = 0; mf < 4; mf++) {
                uint32_t aoff = SWZ((wm * 64 + mf * 16 + offAr) * 128 + (ks * 16 + offAc) * 2);
                uint32_t qh2[4], ql2[4];
                ldm4(qh2, sb + A_QH + aoff);
                ldm4(ql2, sb + A_QL + aoff);
#pragma unroll
                for (int nf = 0; nf < 4; nf++) {
                    int np = nf >> 1, hh = nf & 1;
                    mma_bf(sacc[mf][nf], qh2, kh2[np][hh * 2], kh2[np][hh * 2 + 1]);
                    mma_bf(sacc[mf][nf], qh2, kl2[np][hh * 2], kl2[np][hh * 2 + 1]);
                    mma_bf(sacc[mf][nf], ql2, kh2[np][hh * 2], kh2[np][hh * 2 + 1]);
                }
            }
        }

        // ---- scale + warp row max ----
#pragma unroll
        for (int mf = 0; mf < 4; mf++) {
            float mlo = -INFINITY, mhi = -INFINITY;
#pragma unroll
            for (int nf = 0; nf < 4; nf++) {
#pragma unroll
                for (int e = 0; e < 4; e++) sacc[mf][nf][e] *= SCALE_;
                mlo = fmaxf(mlo, fmaxf(sacc[mf][nf][0], sacc[mf][nf][1]));
                mhi = fmaxf(mhi, fmaxf(sacc[mf][nf][2], sacc[mf][nf][3]));
            }
            mlo = fmaxf(mlo, __shfl_xor_sync(0xffffffffu, mlo, 1));
            mlo = fmaxf(mlo, __shfl_xor_sync(0xffffffffu, mlo, 2));
            mhi = fmaxf(mhi, __shfl_xor_sync(0xffffffffu, mhi, 1));
            mhi = fmaxf(mhi, __shfl_xor_sync(0xffffffffu, mhi, 2));
            if ((lane & 3) == 0) {
                int rl = wm * 64 + mf * 16 + (lane >> 2);
                wmax[wn * 128 + rl] = mlo;
                wmax[wn * 128 + rl + 8] = mhi;
            }
        }
        __syncthreads();

        // ---- p = exp(s - mnew), partial sums, P -> smem split ----
#pragma unroll
        for (int mf = 0; mf < 4; mf++) {
            int rl = wm * 64 + mf * 16 + (lane >> 2), rh = rl + 8;
            float ml = mrun[rl], mh2 = mrun[rh];
#pragma unroll
            for (int w = 0; w < 4; w++) {
                ml = fmaxf(ml, wmax[w * 128 + rl]);
                mh2 = fmaxf(mh2, wmax[w * 128 + rh]);
            }
            float slo = 0.0f, shi = 0.0f;
#pragma unroll
            for (int nf = 0; nf < 4; nf++) {
                float p0 = __expf(sacc[mf][nf][0] - ml);
                float p1 = __expf(sacc[mf][nf][1] - ml);
                float p2 = __expf(sacc[mf][nf][2] - mh2);
                float p3 = __expf(sacc[mf][nf][3] - mh2);
                slo += p0 + p1; shi += p2 + p3;
                int col = wn * 32 + nf * 8 + (lane & 3) * 2;
                int half = col >> 6, cw = col & 63;
                char* basePH = sm + (half ? A_PH1 : A_PH0);
                char* basePL = sm + (half ? A_PL1 : A_PL0);
                bf16 x0, y0, x1, y1;
                splitf(p0, x0, y0); splitf(p1, x1, y1);
                bf162 t, u; t.x = x0; t.y = x1; u.x = y0; u.y = y1;
                *(bf162*)(basePH + SWZ(rl * 128 + cw * 2)) = t;
                *(bf162*)(basePL + SWZ(rl * 128 + cw * 2)) = u;
                splitf(p2, x0, y0); splitf(p3, x1, y1);
                t.x = x0; t.y = x1; u.x = y0; u.y = y1;
                *(bf162*)(basePH + SWZ(rh * 128 + cw * 2)) = t;
                *(bf162*)(basePL + SWZ(rh * 128 + cw * 2)) = u;
            }
            slo += __shfl_xor_sync(0xffffffffu, slo, 1);
            slo += __shfl_xor_sync(0xffffffffu, slo, 2);
            shi += __shfl_xor_sync(0xffffffffu, shi, 1);
            shi += __shfl_xor_sync(0xffffffffu, shi, 2);
            if ((lane & 3) == 0) {
                wsum[wn * 128 + rl] = slo;
                wsum[wn * 128 + rh] = shi;
            }
        }
        __syncthreads();

        // ---- per-row state update (owner thread per row) ----
        if (tid < 128) {
            float mo = mrun[tid], mn = mo;
#pragma unroll
            for (int w = 0; w < 4; w++) mn = fmaxf(mn, wmax[w * 128 + tid]);
            float c = __expf(mo - mn);
            lrun[tid] = lrun[tid] * c + wsum[tid] + wsum[128 + tid] +
                        wsum[256 + tid] + wsum[384 + tid];
            mrun[tid] = mn; crr[tid] = c;
        }
        __syncthreads();

        // ---- O rescale + PV (warp tile 64x16 of O[128,64]) ----
#pragma unroll
        for (int mf = 0; mf < 4; mf++) {
            int rl = wm * 64 + mf * 16 + (lane >> 2);
            float cl_ = crr[rl], ch_ = crr[rl + 8];
#pragma unroll
            for (int nf = 0; nf < 2; nf++) {
                oacc[mf][nf][0] *= cl_; oacc[mf][nf][1] *= cl_;
                oacc[mf][nf][2] *= ch_; oacc[mf][nf][3] *= ch_;
            }
        }
#pragma unroll
        for (int ks = 0; ks < 8; ks++) {
            int key0 = ks * 16;
            uint32_t voff = SWZ((key0 + offAr) * 128 + (wn * 16 + offAc) * 2);
            uint32_t vh2[4], vl2[4];
            ldm4t(vh2, sb + A_VH + voff);
            ldm4t(vl2, sb + A_VL + voff);
            int PHb = (key0 & 64) ? A_PH1 : A_PH0;
            int PLb = (key0 & 64) ? A_PL1 : A_PL0;
#pragma unroll
            for (int mf = 0; mf < 4; mf++) {
                uint32_t poff = SWZ((wm * 64 + mf * 16 + offAr) * 128 +
                                    ((key0 & 63) + offAc) * 2);
                uint32_t ph2[4], pl2[4];
                ldm4(ph2, sb + PHb + poff);
                ldm4(pl2, sb + PLb + poff);
#pragma unroll
                for (int nf = 0; nf < 2; nf++) {
                    mma_bf(oacc[mf][nf], ph2, vh2[nf * 2], vh2[nf * 2 + 1]);
                    mma_bf(oacc[mf][nf], ph2, vl2[nf * 2], vl2[nf * 2 + 1]);
                    mma_bf(oacc[mf][nf], pl2, vh2[nf * 2], vh2[nf * 2 + 1]);
                }
            }
        }
    }

    // ---- epilogue: O /= l, write merged context hi/lo [B*M, 512] ----
    const int b = bh >> 3, h = bh & 7;
#pragma unroll
    for (int mf = 0; mf < 4; mf++) {
        int rl = wm * 64 + mf * 16 + (lane >> 2), rh = rl + 8;
        float il = 1.0f / lrun[rl], ih = 1.0f / lrun[rh];
#pragma unroll
        for (int nf = 0; nf < 2; nf++) {
            int col = wn * 16 + nf * 8 + (lane & 3) * 2;
            size_t blo = ((size_t)b * 2048 + q0 + rl) * 512 + h * 64 + col;
            size_t bhi = ((size_t)b * 2048 + q0 + rh) * 512 + h * 64 + col;
            bf16 x0, y0, x1, y1;
            splitf(oacc[mf][nf][0] * il, x0, y0);
            splitf(oacc[mf][nf][1] * il, x1, y1);
            bf162 t, u; t.x = x0; t.y = x1; u.x = y0; u.y = y1;
            *(bf162*)(Ch + blo) = t; *(bf162*)(Cl + blo) = u;
            splitf(oacc[mf][nf][2] * ih, x0, y0);
            splitf(oacc[mf][nf][3] * ih, x1, y1);
            t.x = x0; t.y = x1; u.x = y0; u.y = y1;
            *(bf162*)(Ch + bhi) = t; *(bf162*)(Cl + bhi) = u;
        }
    }
}

// ---------------------------------------------------------------------------
extern "C" void kernel_launch(void* const* d_in, const int* in_sizes, int n_in,
                              void* d_out, int out_size)
{
    const float* x  = (const float*)d_in[0];
    const float* Wq = (const float*)d_in[1];
    const float* Wk = (const float*)d_in[2];
    const float* Wv = (const float*)d_in[3];
    const float* Wo = (const float*)d_in[4];
    const float* bo = (const float*)d_in[5];
    float* out = (float*)d_out;

    bf16 *Xh, *Xl, *Qh, *Ql, *Kh, *Kl, *Vh, *Vl, *Chp, *Clp, *Whp, *Wlp;
    cudaGetSymbolAddress((void**)&Xh, g_Xh);  cudaGetSymbolAddress((void**)&Xl, g_Xl);
    cudaGetSymbolAddress((void**)&Qh, g_Qh);  cudaGetSymbolAddress((void**)&Ql, g_Ql);
    cudaGetSymbolAddress((void**)&Kh, g_Kh);  cudaGetSymbolAddress((void**)&Kl, g_Kl);
    cudaGetSymbolAddress((void**)&Vh, g_Vh);  cudaGetSymbolAddress((void**)&Vl, g_Vl);
    cudaGetSymbolAddress((void**)&Chp, g_Ch); cudaGetSymbolAddress((void**)&Clp, g_Cl);
    cudaGetSymbolAddress((void**)&Whp, g_Wh); cudaGetSymbolAddress((void**)&Wlp, g_Wl);

    cudaFuncSetAttribute(gemm_mma<0>, cudaFuncAttributeMaxDynamicSharedMemorySize, G_SZ);
    cudaFuncSetAttribute(gemm_mma<2>, cudaFuncAttributeMaxDynamicSharedMemorySize, G_SZ);
    cudaFuncSetAttribute(attn_mma, cudaFuncAttributeMaxDynamicSharedMemorySize, A_SZ);

    // prep
    prep_x<<<(BM_ * HD_ / 4) / 512, 512>>>((const float4*)x, Xh, Xl);
    prep_w<<<512, 512>>>(Wq, Whp + 0 * 262144, Wlp + 0 * 262144);
    prep_w<<<512, 512>>>(Wk, Whp + 1 * 262144, Wlp + 1 * 262144);
    prep_w<<<512, 512>>>(Wv, Whp + 2 * 262144, Wlp + 2 * 262144);
    prep_w<<<512, 512>>>(Wo, Whp + 3 * 262144, Wlp + 3 * 262144);

    // projections -> [b,h,m,d] hi/lo
    dim3 gq(4, 128);
    gemm_mma<0><<<gq, 256, G_SZ>>>(Xh, Xl, Whp + 0 * 262144, Wlp + 0 * 262144,
                                   nullptr, nullptr, Qh, Ql);
    gemm_mma<0><<<gq, 256, G_SZ>>>(Xh, Xl, Whp + 1 * 262144, Wlp + 1 * 262144,
                                   nullptr, nullptr, Kh, Kl);
    gemm_mma<0><<<gq, 256, G_SZ>>>(Xh, Xl, Whp + 2 * 262144, Wlp + 2 * 262144,
                                   nullptr, nullptr, Vh, Vl);

    // attention
    attn_mma<<<dim3(16, 64), 256, A_SZ>>>(Qh, Ql, Kh, Kl, Vh, Vl, Chp, Clp);

    // output projection + bias
    gemm_mma<2><<<gq, 256, G_SZ>>>(Chp, Clp, Whp + 3 * 262144, Wlp + 3 * 262144,
                                   bo, out, nullptr, nullptr);
}

// round 5
// speedup vs baseline: 2.9406x; 1.0532x over previous
#include <cuda_runtime.h>
#include <cuda_bf16.h>
#include <stdint.h>
#include <math.h>

#define B_ 8
#define M_ 2048
#define HD_ 512
#define BM_ (B_*M_)
#define SCALE_ 22.62741699796952f   // reference divides by HEAD_DIM**-0.5

typedef __nv_bfloat16 bf16;
typedef __nv_bfloat162 bf162;

// ---------------- device scratch (allocation-free rule) ----------------
__device__ __align__(16) bf16 g_Xh[(size_t)BM_*HD_], g_Xl[(size_t)BM_*HD_];
__device__ __align__(16) bf16 g_Qh[(size_t)BM_*HD_], g_Ql[(size_t)BM_*HD_];
__device__ __align__(16) bf16 g_Kh[(size_t)BM_*HD_], g_Kl[(size_t)BM_*HD_];
__device__ __align__(16) bf16 g_Vh[(size_t)BM_*HD_], g_Vl[(size_t)BM_*HD_];
__device__ __align__(16) bf16 g_Ch[(size_t)BM_*HD_], g_Cl[(size_t)BM_*HD_];
__device__ __align__(16) bf16 g_Wh[4][512*512], g_Wl[4][512*512];   // W^T: [n][k]

// ---------------- helpers ----------------
__device__ __forceinline__ uint32_t smem_u32(const void* p) {
    uint32_t a;
    asm("{ .reg .u64 t; cvta.to.shared.u64 t, %1; cvt.u32.u64 %0, t; }" : "=r"(a) : "l"(p));
    return a;
}
#define SWZ(x) ((uint32_t)(x) ^ ((((uint32_t)(x)) >> 3) & 0x70))

__device__ __forceinline__ void ldm4(uint32_t (&r)[4], uint32_t a) {
    asm volatile("ldmatrix.sync.aligned.m8n8.x4.shared.b16 {%0,%1,%2,%3}, [%4];"
                 : "=r"(r[0]), "=r"(r[1]), "=r"(r[2]), "=r"(r[3]) : "r"(a));
}
__device__ __forceinline__ void ldm4t(uint32_t (&r)[4], uint32_t a) {
    asm volatile("ldmatrix.sync.aligned.m8n8.x4.trans.shared.b16 {%0,%1,%2,%3}, [%4];"
                 : "=r"(r[0]), "=r"(r[1]), "=r"(r[2]), "=r"(r[3]) : "r"(a));
}
__device__ __forceinline__ void mma_bf(float (&d)[4], const uint32_t (&a)[4],
                                       uint32_t b0, uint32_t b1) {
    asm volatile("mma.sync.aligned.m16n8k16.row.col.f32.bf16.bf16.f32 "
                 "{%0,%1,%2,%3}, {%4,%5,%6,%7}, {%8,%9}, {%0,%1,%2,%3};"
                 : "+f"(d[0]), "+f"(d[1]), "+f"(d[2]), "+f"(d[3])
                 : "r"(a[0]), "r"(a[1]), "r"(a[2]), "r"(a[3]), "r"(b0), "r"(b1));
}
__device__ __forceinline__ void splitf(float x, bf16& h, bf16& l) {
    h = __float2bfloat16(x);
    l = __float2bfloat16(x - __bfloat162float(h));
}
__device__ __forceinline__ void cpa16(uint32_t dst, const void* src) {
    asm volatile("cp.async.cg.shared.global [%0], [%1], 16;" :: "r"(dst), "l"(src));
}
#define CP_COMMIT() asm volatile("cp.async.commit_group;" ::: "memory")
#define CP_WAIT0()  asm volatile("cp.async.wait_group 0;" ::: "memory")

// ---------------- prep kernels ----------------
__global__ void __launch_bounds__(512) prep_x(const float4* __restrict__ x,
                                              bf16* __restrict__ xh, bf16* __restrict__ xl) {
    size_t i = (size_t)blockIdx.x * 512 + threadIdx.x;
    float4 v = x[i];
    bf16 h0, l0, h1, l1, h2, l2, h3, l3;
    splitf(v.x, h0, l0); splitf(v.y, h1, l1);
    splitf(v.z, h2, l2); splitf(v.w, h3, l3);
    bf162 a, b, c, d;
    a.x = h0; a.y = h1; b.x = h2; b.y = h3;
    c.x = l0; c.y = l1; d.x = l2; d.y = l3;
    *(bf162*)(xh + i * 4) = a; *(bf162*)(xh + i * 4 + 2) = b;
    *(bf162*)(xl + i * 4) = c; *(bf162*)(xl + i * 4 + 2) = d;
}

// coalesced tile-transpose: W[k][n] -> W^T[n][k] hi/lo
__global__ void __launch_bounds__(256) prep_w(const float* __restrict__ W,
                                              bf16* __restrict__ th, bf16* __restrict__ tl) {
    __shared__ float t[32][33];
    const int bx = blockIdx.x * 32;   // n-block
    const int by = blockIdx.y * 32;   // k-block
    const int tx = threadIdx.x, ty = threadIdx.y;
#pragma unroll
    for (int j = ty; j < 32; j += 8)
        t[j][tx] = W[(size_t)(by + j) * 512 + bx + tx];   // t[k_local][n_local]
    __syncthreads();
#pragma unroll
    for (int j = ty; j < 32; j += 8) {
        float v = t[tx][j];   // k_local = tx, n_local = j
        bf16 h, l; splitf(v, h, l);
        th[(size_t)(bx + j) * 512 + by + tx] = h;
        tl[(size_t)(bx + j) * 512 + by + tx] = l;
    }
}

// ===========================================================================
// GEMM via mma.sync: C[16384,512] = A(hi/lo [m,512]) @ W^T(hi/lo [n,512])
// CTA 128x128, 8 warps (2x4), warp tile 64x32, split-bf16 3-pass.
// MODE 0: write bf16 hi/lo in [b,h,m,d].   MODE 2: fp32 + bias.
// ===========================================================================
#define G_AH 0
#define G_AL 16384
#define G_BH 32768
#define G_BL 49152
#define G_SZ 65536

template <int MODE>
__global__ void __launch_bounds__(256) gemm_mma(
    const bf16* __restrict__ Ah_, const bf16* __restrict__ Al_,
    const bf16* __restrict__ Bh_, const bf16* __restrict__ Bl_,
    const float* __restrict__ bias, float* __restrict__ out32,
    bf16* __restrict__ oh, bf16* __restrict__ ol)
{
    extern __shared__ char sm[];
    const uint32_t sb = smem_u32(sm);
    const int tid = threadIdx.x, warp = tid >> 5, lane = tid & 31;
    const int wm = warp >> 2, wn = warp & 3;
    const int lr = lane & 7, g = lane >> 3;
    const int offAr = (g & 1) * 8 + lr, offAc = (g >> 1) * 8;
    const int offBr = (g >> 1) * 8 + lr, offBc = (g & 1) * 8;
    const int m0 = blockIdx.y * 128, n0 = blockIdx.x * 128;

    float acc[4][4][4];
#pragma unroll
    for (int a = 0; a < 4; a++)
#pragma unroll
        for (int b = 0; b < 4; b++)
#pragma unroll
            for (int c = 0; c < 4; c++) acc[a][b][c] = 0.0f;

    for (int ch = 0; ch < 8; ch++) {
        if (ch) __syncthreads();
#pragma unroll
        for (int i = 0; i < 4; i++) {
            int t = i * 256 + tid, row = t >> 3, cb = (t & 7) * 16;
            uint32_t dsw = SWZ(row * 128 + cb);
            size_t abyte = ((size_t)(m0 + row) * 512 + ch * 64) * 2 + cb;
            size_t bbyte = ((size_t)(n0 + row) * 512 + ch * 64) * 2 + cb;
            *(uint4*)(sm + G_AH + dsw) = *(const uint4*)((const char*)Ah_ + abyte);
            *(uint4*)(sm + G_AL + dsw) = *(const uint4*)((const char*)Al_ + abyte);
            *(uint4*)(sm + G_BH + dsw) = *(const uint4*)((const char*)Bh_ + bbyte);
            *(uint4*)(sm + G_BL + dsw) = *(const uint4*)((const char*)Bl_ + bbyte);
        }
        __syncthreads();
#pragma unroll
        for (int ks = 0; ks < 4; ks++) {
            uint32_t bhF[2][4], blF[2][4];
#pragma unroll
            for (int np = 0; np < 2; np++) {
                uint32_t boff = SWZ((wn * 32 + np * 16 + offBr) * 128 + (ks * 16 + offBc) * 2);
                ldm4(bhF[np], sb + G_BH + boff);
                ldm4(blF[np], sb + G_BL + boff);
            }
#pragma unroll
            for (int mf = 0; mf < 4; mf++) {
                uint32_t aoff = SWZ((wm * 64 + mf * 16 + offAr) * 128 + (ks * 16 + offAc) * 2);
                uint32_t ah2[4], al2[4];
                ldm4(ah2, sb + G_AH + aoff);
                ldm4(al2, sb + G_AL + aoff);
#pragma unroll
                for (int nf = 0; nf < 4; nf++) {
                    int np = nf >> 1, hh = nf & 1;
                    uint32_t b0h = bhF[np][hh * 2], b1h = bhF[np][hh * 2 + 1];
                    uint32_t b0l = blF[np][hh * 2], b1l = blF[np][hh * 2 + 1];
                    mma_bf(acc[mf][nf], ah2, b0h, b1h);
                    mma_bf(acc[mf][nf], ah2, b0l, b1l);
                    mma_bf(acc[mf][nf], al2, b0h, b1h);
                }
            }
        }
    }

#pragma unroll
    for (int mf = 0; mf < 4; mf++) {
        int rlo = m0 + wm * 64 + mf * 16 + (lane >> 2);
        int rhi = rlo + 8;
#pragma unroll
        for (int nf = 0; nf < 4; nf++) {
            int n = n0 + wn * 32 + nf * 8 + (lane & 3) * 2;
            if (MODE == 2) {
                float2 v0, v1;
                v0.x = acc[mf][nf][0] + bias[n]; v0.y = acc[mf][nf][1] + bias[n + 1];
                v1.x = acc[mf][nf][2] + bias[n]; v1.y = acc[mf][nf][3] + bias[n + 1];
                *(float2*)(out32 + (size_t)rlo * 512 + n) = v0;
                *(float2*)(out32 + (size_t)rhi * 512 + n) = v1;
            } else {
                int h = n >> 6, d = n & 63;
                {
                    int b = rlo >> 11, mm = rlo & 2047;
                    size_t base = ((size_t)(b * 8 + h) * 2048 + mm) * 64 + d;
                    bf16 h0, l0, h1, l1;
                    splitf(acc[mf][nf][0], h0, l0); splitf(acc[mf][nf][1], h1, l1);
                    bf162 t, u; t.x = h0; t.y = h1; u.x = l0; u.y = l1;
                    *(bf162*)(oh + base) = t; *(bf162*)(ol + base) = u;
                }
                {
                    int b = rhi >> 11, mm = rhi & 2047;
                    size_t base = ((size_t)(b * 8 + h) * 2048 + mm) * 64 + d;
                    bf16 h0, l0, h1, l1;
                    splitf(acc[mf][nf][2], h0, l0); splitf(acc[mf][nf][3], h1, l1);
                    bf162 t, u; t.x = h0; t.y = h1; u.x = l0; u.y = l1;
                    *(bf162*)(oh + base) = t; *(bf162*)(ol + base) = u;
                }
            }
        }
    }
}

// ===========================================================================
// Flash attention via mma.sync, 64-key tiles, cp.async double-buffered K/V.
// CTA = (128-q tile, b*h). 256 threads, 8 warps (2x4). 3 barriers/iter.
// ===========================================================================
#define AQH 0
#define AQL 16384
#define AKH(c) (32768 + (c)*8192)
#define AKL(c) (49152 + (c)*8192)
#define AVH(c) (65536 + (c)*8192)
#define AVL(c) (81920 + (c)*8192)
#define APH 98304
#define APL 114688
#define AWMX 131072
#define AWSM 133120
#define ASZ  135168

__global__ void __launch_bounds__(256, 1) attn_mma(
    const bf16* __restrict__ Qh, const bf16* __restrict__ Ql,
    const bf16* __restrict__ Kh, const bf16* __restrict__ Kl,
    const bf16* __restrict__ Vh, const bf16* __restrict__ Vl,
    bf16* __restrict__ Ch, bf16* __restrict__ Cl)
{
    extern __shared__ char sm[];
    const uint32_t sb = smem_u32(sm);
    float* wmax = (float*)(sm + AWMX);   // [4][128]
    float* wsum = (float*)(sm + AWSM);   // [4][128]

    const int tid = threadIdx.x, warp = tid >> 5, lane = tid & 31;
    const int wm = warp >> 2, wn = warp & 3;
    const int lr = lane & 7, g = lane >> 3;
    const int offAr = (g & 1) * 8 + lr, offAc = (g >> 1) * 8;
    const int offBr = (g >> 1) * 8 + lr, offBc = (g & 1) * 8;
    const int bh = blockIdx.y, q0 = blockIdx.x * 128;

    const char* khb = (const char*)Kh + ((size_t)bh * 2048) * 128;
    const char* klb = (const char*)Kl + ((size_t)bh * 2048) * 128;
    const char* vhb = (const char*)Vh + ((size_t)bh * 2048) * 128;
    const char* vlb = (const char*)Vl + ((size_t)bh * 2048) * 128;

    // Q tiles (hi/lo), 128x64
    {
        const char* qhp = (const char*)Qh + ((size_t)bh * 2048 + q0) * 128;
        const char* qlp = (const char*)Ql + ((size_t)bh * 2048 + q0) * 128;
#pragma unroll
        for (int i = 0; i < 4; i++) {
            int t = i * 256 + tid, row = t >> 3, cb = (t & 7) * 16;
            uint32_t dsw = SWZ(row * 128 + cb);
            *(uint4*)(sm + AQH + dsw) = *(const uint4*)(qhp + row * 128 + cb);
            *(uint4*)(sm + AQL + dsw) = *(const uint4*)(qlp + row * 128 + cb);
        }
    }

    // prologue: issue kt=0 loads into buf 0
    {
#pragma unroll
        for (int i = 0; i < 2; i++) {
            int t = i * 256 + tid, row = t >> 3, cb = (t & 7) * 16;
            uint32_t dsw = SWZ(row * 128 + cb);
            size_t go = (size_t)row * 128 + cb;
            cpa16(sb + AKH(0) + dsw, khb + go);
            cpa16(sb + AKL(0) + dsw, klb + go);
            cpa16(sb + AVH(0) + dsw, vhb + go);
            cpa16(sb + AVL(0) + dsw, vlb + go);
        }
        CP_COMMIT();
    }

    float oacc[4][2][4];
#pragma unroll
    for (int a = 0; a < 4; a++)
#pragma unroll
        for (int b = 0; b < 2; b++)
#pragma unroll
            for (int c = 0; c < 4; c++) oacc[a][b][c] = 0.0f;
    float m_prev[8], l_run[8];
#pragma unroll
    for (int r = 0; r < 8; r++) { m_prev[r] = -INFINITY; l_run[r] = 0.0f; }

    for (int kt = 0; kt < 32; kt++) {
        const int c = kt & 1;
        CP_WAIT0();
        __syncthreads();   // buf c ready + all threads done with iter kt-1

        if (kt < 31) {  // prefetch kt+1 into buf c^1 (free since top barrier)
            size_t tb = (size_t)(kt + 1) * 64 * 128;
#pragma unroll
            for (int i = 0; i < 2; i++) {
                int t = i * 256 + tid, row = t >> 3, cb = (t & 7) * 16;
                uint32_t dsw = SWZ(row * 128 + cb);
                size_t go = tb + (size_t)row * 128 + cb;
                cpa16(sb + AKH(c ^ 1) + dsw, khb + go);
                cpa16(sb + AKL(c ^ 1) + dsw, klb + go);
                cpa16(sb + AVH(c ^ 1) + dsw, vhb + go);
                cpa16(sb + AVL(c ^ 1) + dsw, vlb + go);
            }
            CP_COMMIT();
        }

        // ---- S = Q K^T (warp tile 64x16) ----
        float sacc[4][2][4];
#pragma unroll
        for (int a = 0; a < 4; a++)
#pragma unroll
            for (int b = 0; b < 2; b++)
#pragma unroll
                for (int e = 0; e < 4; e++) sacc[a][b][e] = 0.0f;

#pragma unroll
        for (int ks = 0; ks < 4; ks++) {
            uint32_t kh2[4], kl2[4];
            uint32_t boff = SWZ((wn * 16 + offBr) * 128 + (ks * 16 + offBc) * 2);
            ldm4(kh2, sb + AKH(c) + boff);
            ldm4(kl2, sb + AKL(c) + boff);
#pragma unroll
            for (int mf = 0; mf < 4; mf++) {
                uint32_t aoff = SWZ((wm * 64 + mf * 16 + offAr) * 128 + (ks * 16 + offAc) * 2);
                uint32_t qh2[4], ql2[4];
                ldm4(qh2, sb + AQH + aoff);
                ldm4(ql2, sb + AQL + aoff);
#pragma unroll
                for (int nf = 0; nf < 2; nf++) {
                    mma_bf(sacc[mf][nf], qh2, kh2[nf * 2], kh2[nf * 2 + 1]);
                    mma_bf(sacc[mf][nf], qh2, kl2[nf * 2], kl2[nf * 2 + 1]);
                    mma_bf(sacc[mf][nf], ql2, kh2[nf * 2], kh2[nf * 2 + 1]);
                }
            }
        }

        // ---- scale + warp-chunk row max ----
#pragma unroll
        for (int mf = 0; mf < 4; mf++) {
            float mlo = -INFINITY, mhi = -INFINITY;
#pragma unroll
            for (int nf = 0; nf < 2; nf++) {
#pragma unroll
                for (int e = 0; e < 4; e++) sacc[mf][nf][e] *= SCALE_;
                mlo = fmaxf(mlo, fmaxf(sacc[mf][nf][0], sacc[mf][nf][1]));
                mhi = fmaxf(mhi, fmaxf(sacc[mf][nf][2], sacc[mf][nf][3]));
            }
            mlo = fmaxf(mlo, __shfl_xor_sync(0xffffffffu, mlo, 1));
            mlo = fmaxf(mlo, __shfl_xor_sync(0xffffffffu, mlo, 2));
            mhi = fmaxf(mhi, __shfl_xor_sync(0xffffffffu, mhi, 1));
            mhi = fmaxf(mhi, __shfl_xor_sync(0xffffffffu, mhi, 2));
            if ((lane & 3) == 0) {
                int rl = wm * 64 + mf * 16 + (lane >> 2);
                wmax[wn * 128 + rl] = mlo;
                wmax[wn * 128 + rl + 8] = mhi;
            }
        }
        __syncthreads();

        // ---- exp + P store + partial sums ----
        float mlN[4], mhN[4];
#pragma unroll
        for (int mf = 0; mf < 4; mf++) {
            int rl = wm * 64 + mf * 16 + (lane >> 2), rh = rl + 8;
            float ml = m_prev[mf * 2], mh2 = m_prev[mf * 2 + 1];
#pragma unroll
            for (int w = 0; w < 4; w++) {
                ml = fmaxf(ml, wmax[w * 128 + rl]);
                mh2 = fmaxf(mh2, wmax[w * 128 + rh]);
            }
            mlN[mf] = ml; mhN[mf] = mh2;
            float slo = 0.0f, shi = 0.0f;
#pragma unroll
            for (int nf = 0; nf < 2; nf++) {
                float p0 = __expf(sacc[mf][nf][0] - ml);
                float p1 = __expf(sacc[mf][nf][1] - ml);
                float p2 = __expf(sacc[mf][nf][2] - mh2);
                float p3 = __expf(sacc[mf][nf][3] - mh2);
                slo += p0 + p1; shi += p2 + p3;
                int col = wn * 16 + nf * 8 + (lane & 3) * 2;
                bf16 x0, y0, x1, y1;
                splitf(p0, x0, y0); splitf(p1, x1, y1);
                bf162 t, u; t.x = x0; t.y = x1; u.x = y0; u.y = y1;
                *(bf162*)(sm + APH + SWZ(rl * 128 + col * 2)) = t;
                *(bf162*)(sm + APL + SWZ(rl * 128 + col * 2)) = u;
                splitf(p2, x0, y0); splitf(p3, x1, y1);
                t.x = x0; t.y = x1; u.x = y0; u.y = y1;
                *(bf162*)(sm + APH + SWZ(rh * 128 + col * 2)) = t;
                *(bf162*)(sm + APL + SWZ(rh * 128 + col * 2)) = u;
            }
            slo += __shfl_xor_sync(0xffffffffu, slo, 1);
            slo += __shfl_xor_sync(0xffffffffu, slo, 2);
            shi += __shfl_xor_sync(0xffffffffu, shi, 1);
            shi += __shfl_xor_sync(0xffffffffu, shi, 2);
            if ((lane & 3) == 0) {
                wsum[wn * 128 + rl] = slo;
                wsum[wn * 128 + rh] = shi;
            }
        }
        __syncthreads();

        // ---- register state update + O rescale ----
#pragma unroll
        for (int mf = 0; mf < 4; mf++) {
            int rl = wm * 64 + mf * 16 + (lane >> 2), rh = rl + 8;
            float suml = wsum[rl] + wsum[128 + rl] + wsum[256 + rl] + wsum[384 + rl];
            float sumh = wsum[rh] + wsum[128 + rh] + wsum[256 + rh] + wsum[384 + rh];
            float cl_ = __expf(m_prev[mf * 2] - mlN[mf]);
            float ch_ = __expf(m_prev[mf * 2 + 1] - mhN[mf]);
            l_run[mf * 2]     = l_run[mf * 2] * cl_ + suml;
            l_run[mf * 2 + 1] = l_run[mf * 2 + 1] * ch_ + sumh;
            m_prev[mf * 2] = mlN[mf]; m_prev[mf * 2 + 1] = mhN[mf];
#pragma unroll
            for (int nf = 0; nf < 2; nf++) {
                oacc[mf][nf][0] *= cl_; oacc[mf][nf][1] *= cl_;
                oacc[mf][nf][2] *= ch_; oacc[mf][nf][3] *= ch_;
            }
        }

        // ---- PV (O warp tile 64x16) ----
#pragma unroll
        for (int ks = 0; ks < 4; ks++) {
            uint32_t voff = SWZ((ks * 16 + offAr) * 128 + (wn * 16 + offAc) * 2);
            uint32_t vh2[4], vl2[4];
            ldm4t(vh2, sb + AVH(c) + voff);
            ldm4t(vl2, sb + AVL(c) + voff);
#pragma unroll
            for (int mf = 0; mf < 4; mf++) {
                uint32_t poff = SWZ((wm * 64 + mf * 16 + offAr) * 128 + (ks * 16 + offAc) * 2);
                uint32_t ph2[4], pl2[4];
                ldm4(ph2, sb + APH + poff);
                ldm4(pl2, sb + APL + poff);
#pragma unroll
                for (int nf = 0; nf < 2; nf++) {
                    mma_bf(oacc[mf][nf], ph2, vh2[nf * 2], vh2[nf * 2 + 1]);
                    mma_bf(oacc[mf][nf], ph2, vl2[nf * 2], vl2[nf * 2 + 1]);
                    mma_bf(oacc[mf][nf], pl2, vh2[nf * 2], vh2[nf * 2 + 1]);
                }
            }
        }
    }

    // ---- epilogue: O /= l, write merged context hi/lo [B*M, 512] ----
    const int b = bh >> 3, h = bh & 7;
#pragma unroll
    for (int mf = 0; mf < 4; mf++) {
        int rl = wm * 64 + mf * 16 + (lane >> 2), rh = rl + 8;
        float il = 1.0f / l_run[mf * 2], ih = 1.0f / l_run[mf * 2 + 1];
#pragma unroll
        for (int nf = 0; nf < 2; nf++) {
            int col = wn * 16 + nf * 8 + (lane & 3) * 2;
            size_t blo = ((size_t)b * 2048 + q0 + rl) * 512 + h * 64 + col;
            size_t bhi = ((size_t)b * 2048 + q0 + rh) * 512 + h * 64 + col;
            bf16 x0, y0, x1, y1;
            splitf(oacc[mf][nf][0] * il, x0, y0);
            splitf(oacc[mf][nf][1] * il, x1, y1);
            bf162 t, u; t.x = x0; t.y = x1; u.x = y0; u.y = y1;
            *(bf162*)(Ch + blo) = t; *(bf162*)(Cl + blo) = u;
            splitf(oacc[mf][nf][2] * ih, x0, y0);
            splitf(oacc[mf][nf][3] * ih, x1, y1);
            t.x = x0; t.y = x1; u.x = y0; u.y = y1;
            *(bf162*)(Ch + bhi) = t; *(bf162*)(Cl + bhi) = u;
        }
    }
}

// ---------------------------------------------------------------------------
extern "C" void kernel_launch(void* const* d_in, const int* in_sizes, int n_in,
                              void* d_out, int out_size)
{
    const float* x  = (const float*)d_in[0];
    const float* Wq = (const float*)d_in[1];
    const float* Wk = (const float*)d_in[2];
    const float* Wv = (const float*)d_in[3];
    const float* Wo = (const float*)d_in[4];
    const float* bo = (const float*)d_in[5];
    float* out = (float*)d_out;

    bf16 *Xh, *Xl, *Qh, *Ql, *Kh, *Kl, *Vh, *Vl, *Chp, *Clp, *Whp, *Wlp;
    cudaGetSymbolAddress((void**)&Xh, g_Xh);  cudaGetSymbolAddress((void**)&Xl, g_Xl);
    cudaGetSymbolAddress((void**)&Qh, g_Qh);  cudaGetSymbolAddress((void**)&Ql, g_Ql);
    cudaGetSymbolAddress((void**)&Kh, g_Kh);  cudaGetSymbolAddress((void**)&Kl, g_Kl);
    cudaGetSymbolAddress((void**)&Vh, g_Vh);  cudaGetSymbolAddress((void**)&Vl, g_Vl);
    cudaGetSymbolAddress((void**)&Chp, g_Ch); cudaGetSymbolAddress((void**)&Clp, g_Cl);
    cudaGetSymbolAddress((void**)&Whp, g_Wh); cudaGetSymbolAddress((void**)&Wlp, g_Wl);

    cudaFuncSetAttribute(gemm_mma<0>, cudaFuncAttributeMaxDynamicSharedMemorySize, G_SZ);
    cudaFuncSetAttribute(gemm_mma<2>, cudaFuncAttributeMaxDynamicSharedMemorySize, G_SZ);
    cudaFuncSetAttribute(attn_mma, cudaFuncAttributeMaxDynamicSharedMemorySize, ASZ);

    // prep
    prep_x<<<(BM_ * HD_ / 4) / 512, 512>>>((const float4*)x, Xh, Xl);
    dim3 wblk(32, 8), wgrd(16, 16);
    prep_w<<<wgrd, wblk>>>(Wq, Whp + 0 * 262144, Wlp + 0 * 262144);
    prep_w<<<wgrd, wblk>>>(Wk, Whp + 1 * 262144, Wlp + 1 * 262144);
    prep_w<<<wgrd, wblk>>>(Wv, Whp + 2 * 262144, Wlp + 2 * 262144);
    prep_w<<<wgrd, wblk>>>(Wo, Whp + 3 * 262144, Wlp + 3 * 262144);

    // projections -> [b,h,m,d] hi/lo
    dim3 gq(4, 128);
    gemm_mma<0><<<gq, 256, G_SZ>>>(Xh, Xl, Whp + 0 * 262144, Wlp + 0 * 262144,
                                   nullptr, nullptr, Qh, Ql);
    gemm_mma<0><<<gq, 256, G_SZ>>>(Xh, Xl, Whp + 1 * 262144, Wlp + 1 * 262144,
                                   nullptr, nullptr, Kh, Kl);
    gemm_mma<0><<<gq, 256, G_SZ>>>(Xh, Xl, Whp + 2 * 262144, Wlp + 2 * 262144,
                                   nullptr, nullptr, Vh, Vl);

    // attention
    attn_mma<<<dim3(16, 64), 256, ASZ>>>(Qh, Ql, Kh, Kl, Vh, Vl, Chp, Clp);

    // output projection + bias
    gemm_mma<2><<<gq, 256, G_SZ>>>(Chp, Clp, Whp + 3 * 262144, Wlp + 3 * 262144,
                                   bo, out, nullptr, nullptr);
}

// round 6
// speedup vs baseline: 3.2153x; 1.0934x over previous
#include <cuda_runtime.h>
#include <cuda_bf16.h>
#include <stdint.h>
#include <math.h>

#define B_ 8
#define M_ 2048
#define HD_ 512
#define BM_ (B_*M_)
#define SCALE_ 22.62741699796952f   // reference divides by HEAD_DIM**-0.5

typedef __nv_bfloat16 bf16;
typedef __nv_bfloat162 bf162;

// ---------------- device scratch (allocation-free rule) ----------------
__device__ __align__(16) bf16 g_Xh[(size_t)BM_*HD_], g_Xl[(size_t)BM_*HD_];
__device__ __align__(16) bf16 g_Qh[(size_t)BM_*HD_], g_Ql[(size_t)BM_*HD_];
__device__ __align__(16) bf16 g_Kh[(size_t)BM_*HD_], g_Kl[(size_t)BM_*HD_];
__device__ __align__(16) bf16 g_Vh[(size_t)BM_*HD_], g_Vl[(size_t)BM_*HD_];
__device__ __align__(16) bf16 g_Ch[(size_t)BM_*HD_], g_Cl[(size_t)BM_*HD_];
__device__ __align__(16) bf16 g_Wh[4][512*512], g_Wl[4][512*512];   // W^T: [n][k]

// ---------------- helpers ----------------
__device__ __forceinline__ uint32_t smem_u32(const void* p) {
    uint32_t a;
    asm("{ .reg .u64 t; cvta.to.shared.u64 t, %1; cvt.u32.u64 %0, t; }" : "=r"(a) : "l"(p));
    return a;
}
#define SWZ(x) ((uint32_t)(x) ^ ((((uint32_t)(x)) >> 3) & 0x70))

__device__ __forceinline__ void ldm4(uint32_t (&r)[4], uint32_t a) {
    asm volatile("ldmatrix.sync.aligned.m8n8.x4.shared.b16 {%0,%1,%2,%3}, [%4];"
                 : "=r"(r[0]), "=r"(r[1]), "=r"(r[2]), "=r"(r[3]) : "r"(a));
}
__device__ __forceinline__ void ldm4t(uint32_t (&r)[4], uint32_t a) {
    asm volatile("ldmatrix.sync.aligned.m8n8.x4.trans.shared.b16 {%0,%1,%2,%3}, [%4];"
                 : "=r"(r[0]), "=r"(r[1]), "=r"(r[2]), "=r"(r[3]) : "r"(a));
}
__device__ __forceinline__ void mma_bf(float (&d)[4], const uint32_t (&a)[4],
                                       uint32_t b0, uint32_t b1) {
    asm volatile("mma.sync.aligned.m16n8k16.row.col.f32.bf16.bf16.f32 "
                 "{%0,%1,%2,%3}, {%4,%5,%6,%7}, {%8,%9}, {%0,%1,%2,%3};"
                 : "+f"(d[0]), "+f"(d[1]), "+f"(d[2]), "+f"(d[3])
                 : "r"(a[0]), "r"(a[1]), "r"(a[2]), "r"(a[3]), "r"(b0), "r"(b1));
}
__device__ __forceinline__ void splitf(float x, bf16& h, bf16& l) {
    h = __float2bfloat16(x);
    l = __float2bfloat16(x - __bfloat162float(h));
}
__device__ __forceinline__ void cpa16(uint32_t dst, const void* src) {
    asm volatile("cp.async.cg.shared.global [%0], [%1], 16;" :: "r"(dst), "l"(src));
}
#define CP_COMMIT() asm volatile("cp.async.commit_group;" ::: "memory")
#define CP_WAIT0()  asm volatile("cp.async.wait_group 0;" ::: "memory")

// ---------------- prep kernels ----------------
__global__ void __launch_bounds__(512) prep_x(const float4* __restrict__ x,
                                              bf16* __restrict__ xh, bf16* __restrict__ xl) {
    size_t i = (size_t)blockIdx.x * 512 + threadIdx.x;
    float4 v = x[i];
    bf16 h0, l0, h1, l1, h2, l2, h3, l3;
    splitf(v.x, h0, l0); splitf(v.y, h1, l1);
    splitf(v.z, h2, l2); splitf(v.w, h3, l3);
    bf162 a, b, c, d;
    a.x = h0; a.y = h1; b.x = h2; b.y = h3;
    c.x = l0; c.y = l1; d.x = l2; d.y = l3;
    *(bf162*)(xh + i * 4) = a; *(bf162*)(xh + i * 4 + 2) = b;
    *(bf162*)(xl + i * 4) = c; *(bf162*)(xl + i * 4 + 2) = d;
}

// coalesced tile-transpose for all 4 weights: W[k][n] -> W^T[n][k] hi/lo
__global__ void __launch_bounds__(256) prep_w4(
    const float* __restrict__ W0, const float* __restrict__ W1,
    const float* __restrict__ W2, const float* __restrict__ W3,
    bf16* __restrict__ th, bf16* __restrict__ tl) {
    __shared__ float t[32][33];
    const int w = blockIdx.z;
    const float* W = (w == 0) ? W0 : (w == 1) ? W1 : (w == 2) ? W2 : W3;
    bf16* thw = th + (size_t)w * 262144;
    bf16* tlw = tl + (size_t)w * 262144;
    const int bx = blockIdx.x * 32;   // n-block
    const int by = blockIdx.y * 32;   // k-block
    const int tx = threadIdx.x, ty = threadIdx.y;
#pragma unroll
    for (int j = ty; j < 32; j += 8)
        t[j][tx] = W[(size_t)(by + j) * 512 + bx + tx];
    __syncthreads();
#pragma unroll
    for (int j = ty; j < 32; j += 8) {
        float v = t[tx][j];
        bf16 h, l; splitf(v, h, l);
        thw[(size_t)(bx + j) * 512 + by + tx] = h;
        tlw[(size_t)(bx + j) * 512 + by + tx] = l;
    }
}

// ===========================================================================
// GEMM via mma.sync, cp.async double-buffered.
// CTA 128x128, 8 warps (2x4), warp tile 64x32, split-bf16 3-pass.
// MODE 0 (fused QKV): blockIdx.x selects W/output. MODE 2: fp32 + bias.
// ===========================================================================
#define GS(c)   ((c) * 65536)
#define G_AH(c) (GS(c) + 0)
#define G_AL(c) (GS(c) + 16384)
#define G_BH(c) (GS(c) + 32768)
#define G_BL(c) (GS(c) + 49152)
#define G_SZ    131072

template <int MODE>
__global__ void __launch_bounds__(256, 1) gemm_mma(
    const bf16* __restrict__ Ah_, const bf16* __restrict__ Al_,
    const bf16* __restrict__ WhB, const bf16* __restrict__ WlB,
    const float* __restrict__ bias, float* __restrict__ out32,
    bf16* __restrict__ oh0, bf16* __restrict__ ol0,
    bf16* __restrict__ oh1, bf16* __restrict__ ol1,
    bf16* __restrict__ oh2, bf16* __restrict__ ol2)
{
    extern __shared__ char sm[];
    const uint32_t sb = smem_u32(sm);
    const int tid = threadIdx.x, warp = tid >> 5, lane = tid & 31;
    const int wm = warp >> 2, wn = warp & 3;
    const int lr = lane & 7, g = lane >> 3;
    const int offAr = (g & 1) * 8 + lr, offAc = (g >> 1) * 8;
    const int offBr = (g >> 1) * 8 + lr, offBc = (g & 1) * 8;

    const int widx = (MODE == 0) ? (blockIdx.x >> 2) : 0;    // which W / output
    const int n0 = (MODE == 0) ? ((blockIdx.x & 3) * 128) : (blockIdx.x * 128);
    const int m0 = blockIdx.y * 128;
    const bf16* Bh_ = WhB + (size_t)widx * 262144;
    const bf16* Bl_ = WlB + (size_t)widx * 262144;

    // prologue: chunk 0
#pragma unroll
    for (int i = 0; i < 4; i++) {
        int t = i * 256 + tid, row = t >> 3, cb = (t & 7) * 16;
        uint32_t dsw = SWZ(row * 128 + cb);
        size_t abyte = ((size_t)(m0 + row) * 512) * 2 + cb;
        size_t bbyte = ((size_t)(n0 + row) * 512) * 2 + cb;
        cpa16(sb + G_AH(0) + dsw, (const char*)Ah_ + abyte);
        cpa16(sb + G_AL(0) + dsw, (const char*)Al_ + abyte);
        cpa16(sb + G_BH(0) + dsw, (const char*)Bh_ + bbyte);
        cpa16(sb + G_BL(0) + dsw, (const char*)Bl_ + bbyte);
    }
    CP_COMMIT();

    float acc[4][4][4];
#pragma unroll
    for (int a = 0; a < 4; a++)
#pragma unroll
        for (int b = 0; b < 4; b++)
#pragma unroll
            for (int c = 0; c < 4; c++) acc[a][b][c] = 0.0f;

    for (int ch = 0; ch < 8; ch++) {
        const int c = ch & 1;
        CP_WAIT0();
        __syncthreads();          // buf c ready; all warps done with buf c^1

        if (ch < 7) {             // prefetch ch+1 into buf c^1
#pragma unroll
            for (int i = 0; i < 4; i++) {
                int t = i * 256 + tid, row = t >> 3, cb = (t & 7) * 16;
                uint32_t dsw = SWZ(row * 128 + cb);
                size_t abyte = ((size_t)(m0 + row) * 512 + (ch + 1) * 64) * 2 + cb;
                size_t bbyte = ((size_t)(n0 + row) * 512 + (ch + 1) * 64) * 2 + cb;
                cpa16(sb + G_AH(c ^ 1) + dsw, (const char*)Ah_ + abyte);
                cpa16(sb + G_AL(c ^ 1) + dsw, (const char*)Al_ + abyte);
                cpa16(sb + G_BH(c ^ 1) + dsw, (const char*)Bh_ + bbyte);
                cpa16(sb + G_BL(c ^ 1) + dsw, (const char*)Bl_ + bbyte);
            }
            CP_COMMIT();
        }

#pragma unroll
        for (int ks = 0; ks < 4; ks++) {
            uint32_t bhF[2][4], blF[2][4];
#pragma unroll
            for (int np = 0; np < 2; np++) {
                uint32_t boff = SWZ((wn * 32 + np * 16 + offBr) * 128 + (ks * 16 + offBc) * 2);
                ldm4(bhF[np], sb + G_BH(c) + boff);
                ldm4(blF[np], sb + G_BL(c) + boff);
            }
#pragma unroll
            for (int mf = 0; mf < 4; mf++) {
                uint32_t aoff = SWZ((wm * 64 + mf * 16 + offAr) * 128 + (ks * 16 + offAc) * 2);
                uint32_t ah2[4], al2[4];
                ldm4(ah2, sb + G_AH(c) + aoff);
                ldm4(al2, sb + G_AL(c) + aoff);
#pragma unroll
                for (int nf = 0; nf < 4; nf++) {
                    int np = nf >> 1, hh = nf & 1;
                    uint32_t b0h = bhF[np][hh * 2], b1h = bhF[np][hh * 2 + 1];
                    uint32_t b0l = blF[np][hh * 2], b1l = blF[np][hh * 2 + 1];
                    mma_bf(acc[mf][nf], ah2, b0h, b1h);
                    mma_bf(acc[mf][nf], ah2, b0l, b1l);
                    mma_bf(acc[mf][nf], al2, b0h, b1h);
                }
            }
        }
    }

    bf16* oh = (MODE == 0) ? ((widx == 0) ? oh0 : (widx == 1) ? oh1 : oh2) : oh0;
    bf16* ol = (MODE == 0) ? ((widx == 0) ? ol0 : (widx == 1) ? ol1 : ol2) : ol0;

#pragma unroll
    for (int mf = 0; mf < 4; mf++) {
        int rlo = m0 + wm * 64 + mf * 16 + (lane >> 2);
        int rhi = rlo + 8;
#pragma unroll
        for (int nf = 0; nf < 4; nf++) {
            int n = n0 + wn * 32 + nf * 8 + (lane & 3) * 2;
            if (MODE == 2) {
                float2 v0, v1;
                v0.x = acc[mf][nf][0] + bias[n]; v0.y = acc[mf][nf][1] + bias[n + 1];
                v1.x = acc[mf][nf][2] + bias[n]; v1.y = acc[mf][nf][3] + bias[n + 1];
                *(float2*)(out32 + (size_t)rlo * 512 + n) = v0;
                *(float2*)(out32 + (size_t)rhi * 512 + n) = v1;
            } else {
                int h = n >> 6, d = n & 63;
                {
                    int b = rlo >> 11, mm = rlo & 2047;
                    size_t base = ((size_t)(b * 8 + h) * 2048 + mm) * 64 + d;
                    bf16 h0, l0, h1, l1;
                    splitf(acc[mf][nf][0], h0, l0); splitf(acc[mf][nf][1], h1, l1);
                    bf162 t, u; t.x = h0; t.y = h1; u.x = l0; u.y = l1;
                    *(bf162*)(oh + base) = t; *(bf162*)(ol + base) = u;
                }
                {
                    int b = rhi >> 11, mm = rhi & 2047;
                    size_t base = ((size_t)(b * 8 + h) * 2048 + mm) * 64 + d;
                    bf16 h0, l0, h1, l1;
                    splitf(acc[mf][nf][2], h0, l0); splitf(acc[mf][nf][3], h1, l1);
                    bf162 t, u; t.x = h0; t.y = h1; u.x = l0; u.y = l1;
                    *(bf162*)(oh + base) = t; *(bf162*)(ol + base) = u;
                }
            }
        }
    }
}

// ===========================================================================
// Flash attention via mma.sync, 64-key tiles, cp.async double-buffered K/V.
// CTA = (128-q tile, b*h). 512 threads, 16 warps (4 wm x 4 wn), warp tile 32x16.
// ===========================================================================
#define AQH 0
#define AQL 16384
#define AKH(c) (32768 + (c)*32768)
#define AKL(c) (32768 + (c)*32768 + 8192)
#define AVH(c) (32768 + (c)*32768 + 16384)
#define AVL(c) (32768 + (c)*32768 + 24576)
#define APH 98304
#define APL 114688
#define AWMX 131072
#define AWSM 133120
#define ASZ  135168

__global__ void __launch_bounds__(512, 1) attn_mma(
    const bf16* __restrict__ Qh, const bf16* __restrict__ Ql,
    const bf16* __restrict__ Kh, const bf16* __restrict__ Kl,
    const bf16* __restrict__ Vh, const bf16* __restrict__ Vl,
    bf16* __restrict__ Ch, bf16* __restrict__ Cl)
{
    extern __shared__ char sm[];
    const uint32_t sb = smem_u32(sm);
    float* wmax = (float*)(sm + AWMX);   // [4][128]
    float* wsum = (float*)(sm + AWSM);   // [4][128]

    const int tid = threadIdx.x, warp = tid >> 5, lane = tid & 31;
    const int wm = warp >> 2, wn = warp & 3;
    const int lr = lane & 7, g = lane >> 3;
    const int offAr = (g & 1) * 8 + lr, offAc = (g >> 1) * 8;
    const int offBr = (g >> 1) * 8 + lr, offBc = (g & 1) * 8;
    const int bh = blockIdx.y, q0 = blockIdx.x * 128;

    const char* khb = (const char*)Kh + ((size_t)bh * 2048) * 128;
    const char* klb = (const char*)Kl + ((size_t)bh * 2048) * 128;
    const char* vhb = (const char*)Vh + ((size_t)bh * 2048) * 128;
    const char* vlb = (const char*)Vl + ((size_t)bh * 2048) * 128;

    // Q tiles (hi/lo), 128x64
    {
        const char* qhp = (const char*)Qh + ((size_t)bh * 2048 + q0) * 128;
        const char* qlp = (const char*)Ql + ((size_t)bh * 2048 + q0) * 128;
#pragma unroll
        for (int i = 0; i < 2; i++) {
            int t = i * 512 + tid, row = t >> 3, cb = (t & 7) * 16;
            uint32_t dsw = SWZ(row * 128 + cb);
            *(uint4*)(sm + AQH + dsw) = *(const uint4*)(qhp + row * 128 + cb);
            *(uint4*)(sm + AQL + dsw) = *(const uint4*)(qlp + row * 128 + cb);
        }
    }

    // prologue: issue kt=0 loads into buf 0 (each thread: 16B per array)
    {
        int row = tid >> 3, cb = (tid & 7) * 16;
        uint32_t dsw = SWZ(row * 128 + cb);
        size_t go = (size_t)row * 128 + cb;
        cpa16(sb + AKH(0) + dsw, khb + go);
        cpa16(sb + AKL(0) + dsw, klb + go);
        cpa16(sb + AVH(0) + dsw, vhb + go);
        cpa16(sb + AVL(0) + dsw, vlb + go);
        CP_COMMIT();
    }

    float oacc[2][2][4];
#pragma unroll
    for (int a = 0; a < 2; a++)
#pragma unroll
        for (int b = 0; b < 2; b++)
#pragma unroll
            for (int c = 0; c < 4; c++) oacc[a][b][c] = 0.0f;
    float m_prev[4], l_run[4];
#pragma unroll
    for (int r = 0; r < 4; r++) { m_prev[r] = -INFINITY; l_run[r] = 0.0f; }

    for (int kt = 0; kt < 32; kt++) {
        const int c = kt & 1;
        CP_WAIT0();
        __syncthreads();   // buf c ready + all threads done with iter kt-1

        if (kt < 31) {     // prefetch kt+1 into buf c^1
            size_t tb = (size_t)(kt + 1) * 64 * 128;
            int row = tid >> 3, cb = (tid & 7) * 16;
            uint32_t dsw = SWZ(row * 128 + cb);
            size_t go = tb + (size_t)row * 128 + cb;
            cpa16(sb + AKH(c ^ 1) + dsw, khb + go);
            cpa16(sb + AKL(c ^ 1) + dsw, klb + go);
            cpa16(sb + AVH(c ^ 1) + dsw, vhb + go);
            cpa16(sb + AVL(c ^ 1) + dsw, vlb + go);
            CP_COMMIT();
        }

        // ---- S = Q K^T (warp tile 32x16) ----
        float sacc[2][2][4];
#pragma unroll
        for (int a = 0; a < 2; a++)
#pragma unroll
            for (int b = 0; b < 2; b++)
#pragma unroll
                for (int e = 0; e < 4; e++) sacc[a][b][e] = 0.0f;

#pragma unroll
        for (int ks = 0; ks < 4; ks++) {
            uint32_t kh2[4], kl2[4];
            uint32_t boff = SWZ((wn * 16 + offBr) * 128 + (ks * 16 + offBc) * 2);
            ldm4(kh2, sb + AKH(c) + boff);
            ldm4(kl2, sb + AKL(c) + boff);
#pragma unroll
            for (int mf = 0; mf < 2; mf++) {
                uint32_t aoff = SWZ((wm * 32 + mf * 16 + offAr) * 128 + (ks * 16 + offAc) * 2);
                uint32_t qh2[4], ql2[4];
                ldm4(qh2, sb + AQH + aoff);
                ldm4(ql2, sb + AQL + aoff);
#pragma unroll
                for (int nf = 0; nf < 2; nf++) {
                    mma_bf(sacc[mf][nf], qh2, kh2[nf * 2], kh2[nf * 2 + 1]);
                    mma_bf(sacc[mf][nf], qh2, kl2[nf * 2], kl2[nf * 2 + 1]);
                    mma_bf(sacc[mf][nf], ql2, kh2[nf * 2], kh2[nf * 2 + 1]);
                }
            }
        }

        // ---- scale + warp-chunk row max ----
#pragma unroll
        for (int mf = 0; mf < 2; mf++) {
            float mlo = -INFINITY, mhi = -INFINITY;
#pragma unroll
            for (int nf = 0; nf < 2; nf++) {
#pragma unroll
                for (int e = 0; e < 4; e++) sacc[mf][nf][e] *= SCALE_;
                mlo = fmaxf(mlo, fmaxf(sacc[mf][nf][0], sacc[mf][nf][1]));
                mhi = fmaxf(mhi, fmaxf(sacc[mf][nf][2], sacc[mf][nf][3]));
            }
            mlo = fmaxf(mlo, __shfl_xor_sync(0xffffffffu, mlo, 1));
            mlo = fmaxf(mlo, __shfl_xor_sync(0xffffffffu, mlo, 2));
            mhi = fmaxf(mhi, __shfl_xor_sync(0xffffffffu, mhi, 1));
            mhi = fmaxf(mhi, __shfl_xor_sync(0xffffffffu, mhi, 2));
            if ((lane & 3) == 0) {
                int rl = wm * 32 + mf * 16 + (lane >> 2);
                wmax[wn * 128 + rl] = mlo;
                wmax[wn * 128 + rl + 8] = mhi;
            }
        }
        __syncthreads();

        // ---- exp + P store + partial sums ----
        float mlN[2], mhN[2];
#pragma unroll
        for (int mf = 0; mf < 2; mf++) {
            int rl = wm * 32 + mf * 16 + (lane >> 2), rh = rl + 8;
            float ml = m_prev[mf * 2], mh2 = m_prev[mf * 2 + 1];
#pragma unroll
            for (int w = 0; w < 4; w++) {
                ml = fmaxf(ml, wmax[w * 128 + rl]);
                mh2 = fmaxf(mh2, wmax[w * 128 + rh]);
            }
            mlN[mf] = ml; mhN[mf] = mh2;
            float slo = 0.0f, shi = 0.0f;
#pragma unroll
            for (int nf = 0; nf < 2; nf++) {
                float p0 = __expf(sacc[mf][nf][0] - ml);
                float p1 = __expf(sacc[mf][nf][1] - ml);
                float p2 = __expf(sacc[mf][nf][2] - mh2);
                float p3 = __expf(sacc[mf][nf][3] - mh2);
                slo += p0 + p1; shi += p2 + p3;
                int col = wn * 16 + nf * 8 + (lane & 3) * 2;
                bf16 x0, y0, x1, y1;
                splitf(p0, x0, y0); splitf(p1, x1, y1);
                bf162 t, u; t.x = x0; t.y = x1; u.x = y0; u.y = y1;
                *(bf162*)(sm + APH + SWZ(rl * 128 + col * 2)) = t;
                *(bf162*)(sm + APL + SWZ(rl * 128 + col * 2)) = u;
                splitf(p2, x0, y0); splitf(p3, x1, y1);
                t.x = x0; t.y = x1; u.x = y0; u.y = y1;
                *(bf162*)(sm + APH + SWZ(rh * 128 + col * 2)) = t;
                *(bf162*)(sm + APL + SWZ(rh * 128 + col * 2)) = u;
            }
            slo += __shfl_xor_sync(0xffffffffu, slo, 1);
            slo += __shfl_xor_sync(0xffffffffu, slo, 2);
            shi += __shfl_xor_sync(0xffffffffu, shi, 1);
            shi += __shfl_xor_sync(0xffffffffu, shi, 2);
            if ((lane & 3) == 0) {
                wsum[wn * 128 + rl] = slo;
                wsum[wn * 128 + rh] = shi;
            }
        }
        __syncthreads();

        // ---- register state update + O rescale ----
#pragma unroll
        for (int mf = 0; mf < 2; mf++) {
            int rl = wm * 32 + mf * 16 + (lane >> 2), rh = rl + 8;
            float suml = wsum[rl] + wsum[128 + rl] + wsum[256 + rl] + wsum[384 + rl];
            float sumh = wsum[rh] + wsum[128 + rh] + wsum[256 + rh] + wsum[384 + rh];
            float cl_ = __expf(m_prev[mf * 2] - mlN[mf]);
            float ch_ = __expf(m_prev[mf * 2 + 1] - mhN[mf]);
            l_run[mf * 2]     = l_run[mf * 2] * cl_ + suml;
            l_run[mf * 2 + 1] = l_run[mf * 2 + 1] * ch_ + sumh;
            m_prev[mf * 2] = mlN[mf]; m_prev[mf * 2 + 1] = mhN[mf];
#pragma unroll
            for (int nf = 0; nf < 2; nf++) {
                oacc[mf][nf][0] *= cl_; oacc[mf][nf][1] *= cl_;
                oacc[mf][nf][2] *= ch_; oacc[mf][nf][3] *= ch_;
            }
        }

        // ---- PV (O warp tile 32x16) ----
#pragma unroll
        for (int ks = 0; ks < 4; ks++) {
            uint32_t voff = SWZ((ks * 16 + offAr) * 128 + (wn * 16 + offAc) * 2);
            uint32_t vh2[4], vl2[4];
            ldm4t(vh2, sb + AVH(c) + voff);
            ldm4t(vl2, sb + AVL(c) + voff);
#pragma unroll
            for (int mf = 0; mf < 2; mf++) {
                uint32_t poff = SWZ((wm * 32 + mf * 16 + offAr) * 128 + (ks * 16 + offAc) * 2);
                uint32_t ph2[4], pl2[4];
                ldm4(ph2, sb + APH + poff);
                ldm4(pl2, sb + APL + poff);
#pragma unroll
                for (int nf = 0; nf < 2; nf++) {
                    mma_bf(oacc[mf][nf], ph2, vh2[nf * 2], vh2[nf * 2 + 1]);
                    mma_bf(oacc[mf][nf], ph2, vl2[nf * 2], vl2[nf * 2 + 1]);
                    mma_bf(oacc[mf][nf], pl2, vh2[nf * 2], vh2[nf * 2 + 1]);
                }
            }
        }
    }

    // ---- epilogue: O /= l, write merged context hi/lo [B*M, 512] ----
    const int b = bh >> 3, h = bh & 7;
#pragma unroll
    for (int mf = 0; mf < 2; mf++) {
        int rl = wm * 32 + mf * 16 + (lane >> 2), rh = rl + 8;
        float il = 1.0f / l_run[mf * 2], ih = 1.0f / l_run[mf * 2 + 1];
#pragma unroll
        for (int nf = 0; nf < 2; nf++) {
            int col = wn * 16 + nf * 8 + (lane & 3) * 2;
            size_t blo = ((size_t)b * 2048 + q0 + rl) * 512 + h * 64 + col;
            size_t bhi = ((size_t)b * 2048 + q0 + rh) * 512 + h * 64 + col;
            bf16 x0, y0, x1, y1;
            splitf(oacc[mf][nf][0] * il, x0, y0);
            splitf(oacc[mf][nf][1] * il, x1, y1);
            bf162 t, u; t.x = x0; t.y = x1; u.x = y0; u.y = y1;
            *(bf162*)(Ch + blo) = t; *(bf162*)(Cl + blo) = u;
            splitf(oacc[mf][nf][2] * ih, x0, y0);
            splitf(oacc[mf][nf][3] * ih, x1, y1);
            t.x = x0; t.y = x1; u.x = y0; u.y = y1;
            *(bf162*)(Ch + bhi) = t; *(bf162*)(Cl + bhi) = u;
        }
    }
}

// ---------------------------------------------------------------------------
extern "C" void kernel_launch(void* const* d_in, const int* in_sizes, int n_in,
                              void* d_out, int out_size)
{
    const float* x  = (const float*)d_in[0];
    const float* Wq = (const float*)d_in[1];
    const float* Wk = (const float*)d_in[2];
    const float* Wv = (const float*)d_in[3];
    const float* Wo = (const float*)d_in[4];
    const float* bo = (const float*)d_in[5];
    float* out = (float*)d_out;

    bf16 *Xh, *Xl, *Qh, *Ql, *Kh, *Kl, *Vh, *Vl, *Chp, *Clp, *Whp, *Wlp;
    cudaGetSymbolAddress((void**)&Xh, g_Xh);  cudaGetSymbolAddress((void**)&Xl, g_Xl);
    cudaGetSymbolAddress((void**)&Qh, g_Qh);  cudaGetSymbolAddress((void**)&Ql, g_Ql);
    cudaGetSymbolAddress((void**)&Kh, g_Kh);  cudaGetSymbolAddress((void**)&Kl, g_Kl);
    cudaGetSymbolAddress((void**)&Vh, g_Vh);  cudaGetSymbolAddress((void**)&Vl, g_Vl);
    cudaGetSymbolAddress((void**)&Chp, g_Ch); cudaGetSymbolAddress((void**)&Clp, g_Cl);
    cudaGetSymbolAddress((void**)&Whp, g_Wh); cudaGetSymbolAddress((void**)&Wlp, g_Wl);

    cudaFuncSetAttribute(gemm_mma<0>, cudaFuncAttributeMaxDynamicSharedMemorySize, G_SZ);
    cudaFuncSetAttribute(gemm_mma<2>, cudaFuncAttributeMaxDynamicSharedMemorySize, G_SZ);
    cudaFuncSetAttribute(attn_mma, cudaFuncAttributeMaxDynamicSharedMemorySize, ASZ);

    // prep
    prep_x<<<(BM_ * HD_ / 4) / 512, 512>>>((const float4*)x, Xh, Xl);
    dim3 wblk(32, 8), wgrd(16, 16, 4);
    prep_w4<<<wgrd, wblk>>>(Wq, Wk, Wv, Wo, Whp, Wlp);

    // fused QKV projections -> [b,h,m,d] hi/lo
    gemm_mma<0><<<dim3(12, 128), 256, G_SZ>>>(Xh, Xl, Whp, Wlp,
                                              nullptr, nullptr,
                                              Qh, Ql, Kh, Kl, Vh, Vl);

    // attention
    attn_mma<<<dim3(16, 64), 512, ASZ>>>(Qh, Ql, Kh, Kl, Vh, Vl, Chp, Clp);

    // output projection + bias
    gemm_mma<2><<<dim3(4, 128), 256, G_SZ>>>(Chp, Clp, Whp + 3 * 262144, Wlp + 3 * 262144,
                                             bo, out, nullptr, nullptr,
                                             nullptr, nullptr, nullptr, nullptr);
}